// round 5
// baseline (speedup 1.0000x reference)
#include <cuda_runtime.h>
#include <math.h>

// Problem dims
#define Bc 64
#define Tc 512
#define Ic 512
#define Hc 1024
#define Oc 512
#define NCTA 128   // persistent grid for recurrence (<=148 SMs -> co-resident)

// Scratch (static __device__ allowed; cudaMalloc is not)
__device__ float g_xw[Tc * Bc * Hc];    // [t][b][h]  x@W_xh + b_h
__device__ float g_hall[Tc * Bc * Hc];  // [t][b][h]  hidden states
__device__ unsigned g_bar;

// ---------------------------------------------------------------------------
// init: reset barrier counter each launch (graph replays must be deterministic)
// ---------------------------------------------------------------------------
__global__ void k_init() {
    if (threadIdx.x == 0) g_bar = 0u;
}

// ---------------------------------------------------------------------------
// GEMM 1: g_xw[t*B+b][h] = x[b*T+t][:] @ W_xh[:, h] + b_h[h]
// M=32768, N=1024, K=512. 128x128 tile, BK=8, 256 thr, 8x8 per thread.
// ---------------------------------------------------------------------------
__global__ void __launch_bounds__(256) k_gemm_xw(const float* __restrict__ A,
                                                 const float* __restrict__ Bm,
                                                 const float* __restrict__ bias) {
    __shared__ float As[8][128];
    __shared__ float Bs[8][128];
    const int tid = threadIdx.x;
    const int tx = tid & 15;   // n
    const int ty = tid >> 4;   // m
    const int m0 = blockIdx.y * 128;
    const int n0 = blockIdx.x * 128;

    const int ar = tid >> 1, ac = (tid & 1) * 4;   // A: 128 rows x 8 k
    const int br = tid >> 5, bc = (tid & 31) * 4;  // B: 8 k x 128 n

    float acc[8][8];
#pragma unroll
    for (int i = 0; i < 8; ++i)
#pragma unroll
        for (int j = 0; j < 8; ++j) acc[i][j] = 0.f;

    for (int k0 = 0; k0 < Ic; k0 += 8) {
        float4 av = *(const float4*)&A[(size_t)(m0 + ar) * Ic + k0 + ac];
        float4 bv = *(const float4*)&Bm[(size_t)(k0 + br) * Hc + n0 + bc];
        __syncthreads();
        As[ac + 0][ar] = av.x; As[ac + 1][ar] = av.y;
        As[ac + 2][ar] = av.z; As[ac + 3][ar] = av.w;
        *(float4*)&Bs[br][bc] = bv;
        __syncthreads();
#pragma unroll
        for (int k = 0; k < 8; ++k) {
            float4 a0 = *(const float4*)&As[k][ty * 8];
            float4 a1 = *(const float4*)&As[k][ty * 8 + 4];
            float4 b0 = *(const float4*)&Bs[k][tx * 8];
            float4 b1 = *(const float4*)&Bs[k][tx * 8 + 4];
            float ra[8] = {a0.x, a0.y, a0.z, a0.w, a1.x, a1.y, a1.z, a1.w};
            float rb[8] = {b0.x, b0.y, b0.z, b0.w, b1.x, b1.y, b1.z, b1.w};
#pragma unroll
            for (int i = 0; i < 8; ++i)
#pragma unroll
                for (int j = 0; j < 8; ++j)
                    acc[i][j] = fmaf(ra[i], rb[j], acc[i][j]);
        }
    }
#pragma unroll
    for (int i = 0; i < 8; ++i) {
        int r = m0 + ty * 8 + i;       // r = b*T + t
        int b = r >> 9;                // /512
        int t = r & 511;
        float* orow = g_xw + (size_t)(t * Bc + b) * Hc + n0 + tx * 8;
#pragma unroll
        for (int j = 0; j < 8; ++j)
            orow[j] = acc[i][j] + bias[n0 + tx * 8 + j];
    }
}

// ---------------------------------------------------------------------------
// GEMM 2: out[b][t][o] = g_hall[t*B+b][:] @ W_hy[:, o] + b_y[o]
// M=32768, N=512, K=1024.
// ---------------------------------------------------------------------------
__global__ void __launch_bounds__(256) k_gemm_y(const float* __restrict__ Bm,
                                                const float* __restrict__ bias,
                                                float* __restrict__ out) {
    __shared__ float As[8][128];
    __shared__ float Bs[8][128];
    const int tid = threadIdx.x;
    const int tx = tid & 15;
    const int ty = tid >> 4;
    const int m0 = blockIdx.y * 128;
    const int n0 = blockIdx.x * 128;

    const int ar = tid >> 1, ac = (tid & 1) * 4;
    const int br = tid >> 5, bc = (tid & 31) * 4;

    float acc[8][8];
#pragma unroll
    for (int i = 0; i < 8; ++i)
#pragma unroll
        for (int j = 0; j < 8; ++j) acc[i][j] = 0.f;

    const float* A = g_hall;  // rows r = t*B + b, contiguous [32768,1024]
    for (int k0 = 0; k0 < Hc; k0 += 8) {
        float4 av = *(const float4*)&A[(size_t)(m0 + ar) * Hc + k0 + ac];
        float4 bv = *(const float4*)&Bm[(size_t)(k0 + br) * Oc + n0 + bc];
        __syncthreads();
        As[ac + 0][ar] = av.x; As[ac + 1][ar] = av.y;
        As[ac + 2][ar] = av.z; As[ac + 3][ar] = av.w;
        *(float4*)&Bs[br][bc] = bv;
        __syncthreads();
#pragma unroll
        for (int k = 0; k < 8; ++k) {
            float4 a0 = *(const float4*)&As[k][ty * 8];
            float4 a1 = *(const float4*)&As[k][ty * 8 + 4];
            float4 b0 = *(const float4*)&Bs[k][tx * 8];
            float4 b1 = *(const float4*)&Bs[k][tx * 8 + 4];
            float ra[8] = {a0.x, a0.y, a0.z, a0.w, a1.x, a1.y, a1.z, a1.w};
            float rb[8] = {b0.x, b0.y, b0.z, b0.w, b1.x, b1.y, b1.z, b1.w};
#pragma unroll
            for (int i = 0; i < 8; ++i)
#pragma unroll
                for (int j = 0; j < 8; ++j)
                    acc[i][j] = fmaf(ra[i], rb[j], acc[i][j]);
        }
    }
#pragma unroll
    for (int i = 0; i < 8; ++i) {
        int r = m0 + ty * 8 + i;       // r = t*B + b
        int t = r >> 6;                // /64
        int b = r & 63;
        float* orow = out + ((size_t)b * Tc + t) * Oc + n0 + tx * 8;
#pragma unroll
        for (int j = 0; j < 8; ++j)
            orow[j] = acc[i][j] + bias[n0 + tx * 8 + j];
    }
}

// ---------------------------------------------------------------------------
// Persistent recurrence kernel.
// 128 CTAs x 256 threads. CTA c owns W_hh columns [c*8, c*8+8), preloaded
// into SMEM once (constant across time). Per step: stream h_{t-1} through
// SMEM in 128-wide K chunks, each thread computes 2 output columns for one
// batch row, tanh, store, grid barrier.
// ---------------------------------------------------------------------------
__global__ void __launch_bounds__(256, 1) k_rnn(const float* __restrict__ Whh) {
    extern __shared__ float sm[];
    float* w_sh = sm;                 // [8][1024]
    float* h_sh = sm + 8 * 1024;      // [64][129] (pad for bank-conflict-free)

    const int tid = threadIdx.x;
    const int j0 = blockIdx.x * 8;
    const int row = tid & 63;         // batch row 0..63
    const int cg = tid >> 6;          // 0..3
    const int c0 = cg * 2, c1 = c0 + 1;

    // Preload this CTA's 8 W_hh columns: w_sh[c][k] = Whh[k][j0+c]
    for (int e = tid; e < 8 * 1024; e += 256) {
        int c = e & 7, k = e >> 3;
        w_sh[c * 1024 + k] = Whh[(size_t)k * Hc + j0 + c];
    }
    __syncthreads();

    const float* wc0 = w_sh + c0 * 1024;
    const float* wc1 = w_sh + c1 * 1024;

    unsigned target = NCTA;
    for (int t = 0; t < Tc; ++t) {
        float acc0 = 0.f, acc1 = 0.f;
        if (t > 0) {
            const float* hprev = g_hall + (size_t)(t - 1) * (Bc * Hc);
            for (int kk = 0; kk < Hc; kk += 128) {
                __syncthreads();
#pragma unroll
                for (int i = 0; i < 32; ++i) {   // 64*128 / 256 threads
                    int e = tid + i * 256;
                    int b = e >> 7, kc = e & 127;
                    h_sh[b * 129 + kc] = hprev[b * Hc + kk + kc];
                }
                __syncthreads();
                const float* hr = h_sh + row * 129;
                const float* w0 = wc0 + kk;
                const float* w1 = wc1 + kk;
#pragma unroll 32
                for (int kc = 0; kc < 128; ++kc) {
                    float hv = hr[kc];
                    acc0 = fmaf(hv, w0[kc], acc0);
                    acc1 = fmaf(hv, w1[kc], acc1);
                }
            }
        }
        // epilogue: add input projection (b_h already folded in), tanh, store
        const float* xwt = g_xw + (size_t)(t * Bc + row) * Hc + j0;
        float h0 = tanhf(acc0 + xwt[c0]);
        float h1 = tanhf(acc1 + xwt[c1]);
        float* hout = g_hall + (size_t)(t * Bc + row) * Hc + j0;
        hout[c0] = h0;
        hout[c1] = h1;

        // grid barrier (all 128 CTAs co-resident; monotone counter, reset by k_init)
        __syncthreads();
        if (tid == 0) {
            __threadfence();
            atomicAdd(&g_bar, 1u);
            while (*((volatile unsigned*)&g_bar) < target) { }
            __threadfence();
        }
        __syncthreads();
        target += NCTA;
    }
}

// ---------------------------------------------------------------------------
extern "C" void kernel_launch(void* const* d_in, const int* in_sizes, int n_in,
                              void* d_out, int out_size) {
    const float* x    = (const float*)d_in[0];  // [64,512,512]
    const float* W_xh = (const float*)d_in[1];  // [512,1024]
    const float* W_hh = (const float*)d_in[2];  // [1024,1024]
    const float* b_h  = (const float*)d_in[3];  // [1024]
    const float* W_hy = (const float*)d_in[4];  // [1024,512]
    const float* b_y  = (const float*)d_in[5];  // [512]
    float* out = (float*)d_out;                 // [64,512,512]

    static bool attr_set = false;
    if (!attr_set) {
        cudaFuncSetAttribute(k_rnn, cudaFuncAttributeMaxDynamicSharedMemorySize,
                             (8 * 1024 + 64 * 129) * (int)sizeof(float));
        attr_set = true;
    }

    k_init<<<1, 32>>>();

    // xW projection: M=32768, N=1024
    dim3 gx(Hc / 128, (Bc * Tc) / 128);
    k_gemm_xw<<<gx, 256>>>(x, W_xh, b_h);

    // recurrence: persistent, 128 CTAs
    size_t smem = (8 * 1024 + 64 * 129) * sizeof(float);
    k_rnn<<<NCTA, 256, smem>>>(W_hh);

    // output projection: M=32768, N=512
    dim3 gy(Oc / 128, (Bc * Tc) / 128);
    k_gemm_y<<<gy, 256>>>(W_hy, b_y, out);
}

// round 6
// speedup vs baseline: 1.4253x; 1.4253x over previous
#include <cuda_runtime.h>
#include <math.h>

// Problem dims
#define Bc 64
#define Tc 512
#define Ic 512
#define Hc 1024
#define Oc 512
#define NCTA 128   // persistent grid (<=148 SMs -> all co-resident)

// Recurrence decomposition
#define NT 8       // column tiles of 128
#define KC 16      // K chunks of 64
#define KCH 64     // k per chunk
#define CT 128     // cols per tile
#define HSTRIDE 72 // padded row stride for transposed h in smem (16B aligned)

// Scratch (static __device__ allowed; cudaMalloc is not)
__device__ float g_xw[Tc * Bc * Hc];     // [t][b][h]  x@W_xh + b_h
__device__ float g_hall[Tc * Bc * Hc];   // [t][b][h]  hidden states
__device__ float g_part[KC * Bc * Hc];   // [kc][b][h] per-K-chunk partial sums (4MB)
__device__ unsigned g_bar;

// ---------------------------------------------------------------------------
__global__ void k_init() {
    if (threadIdx.x == 0) g_bar = 0u;
}

// ---------------------------------------------------------------------------
// GEMM 1: g_xw[t*B+b][h] = x[b*T+t][:] @ W_xh[:, h] + b_h[h]
// M=32768, N=1024, K=512. 128x128 tile, BK=8, 256 thr, 8x8 per thread.
// ---------------------------------------------------------------------------
__global__ void __launch_bounds__(256) k_gemm_xw(const float* __restrict__ A,
                                                 const float* __restrict__ Bm,
                                                 const float* __restrict__ bias) {
    __shared__ float As[8][128];
    __shared__ float Bs[8][128];
    const int tid = threadIdx.x;
    const int tx = tid & 15;   // n
    const int ty = tid >> 4;   // m
    const int m0 = blockIdx.y * 128;
    const int n0 = blockIdx.x * 128;

    const int ar = tid >> 1, ac = (tid & 1) * 4;   // A: 128 rows x 8 k
    const int br = tid >> 5, bc = (tid & 31) * 4;  // B: 8 k x 128 n

    float acc[8][8];
#pragma unroll
    for (int i = 0; i < 8; ++i)
#pragma unroll
        for (int j = 0; j < 8; ++j) acc[i][j] = 0.f;

    for (int k0 = 0; k0 < Ic; k0 += 8) {
        float4 av = *(const float4*)&A[(size_t)(m0 + ar) * Ic + k0 + ac];
        float4 bv = *(const float4*)&Bm[(size_t)(k0 + br) * Hc + n0 + bc];
        __syncthreads();
        As[ac + 0][ar] = av.x; As[ac + 1][ar] = av.y;
        As[ac + 2][ar] = av.z; As[ac + 3][ar] = av.w;
        *(float4*)&Bs[br][bc] = bv;
        __syncthreads();
#pragma unroll
        for (int k = 0; k < 8; ++k) {
            float4 a0 = *(const float4*)&As[k][ty * 8];
            float4 a1 = *(const float4*)&As[k][ty * 8 + 4];
            float4 b0 = *(const float4*)&Bs[k][tx * 8];
            float4 b1 = *(const float4*)&Bs[k][tx * 8 + 4];
            float ra[8] = {a0.x, a0.y, a0.z, a0.w, a1.x, a1.y, a1.z, a1.w};
            float rb[8] = {b0.x, b0.y, b0.z, b0.w, b1.x, b1.y, b1.z, b1.w};
#pragma unroll
            for (int i = 0; i < 8; ++i)
#pragma unroll
                for (int j = 0; j < 8; ++j)
                    acc[i][j] = fmaf(ra[i], rb[j], acc[i][j]);
        }
    }
#pragma unroll
    for (int i = 0; i < 8; ++i) {
        int r = m0 + ty * 8 + i;       // r = b*T + t
        int b = r >> 9;                // /512
        int t = r & 511;
        float* orow = g_xw + (size_t)(t * Bc + b) * Hc + n0 + tx * 8;
#pragma unroll
        for (int j = 0; j < 8; ++j)
            orow[j] = acc[i][j] + bias[n0 + tx * 8 + j];
    }
}

// ---------------------------------------------------------------------------
// GEMM 2: out[b][t][o] = g_hall[t*B+b][:] @ W_hy[:, o] + b_y[o]
// M=32768, N=512, K=1024.
// ---------------------------------------------------------------------------
__global__ void __launch_bounds__(256) k_gemm_y(const float* __restrict__ Bm,
                                                const float* __restrict__ bias,
                                                float* __restrict__ out) {
    __shared__ float As[8][128];
    __shared__ float Bs[8][128];
    const int tid = threadIdx.x;
    const int tx = tid & 15;
    const int ty = tid >> 4;
    const int m0 = blockIdx.y * 128;
    const int n0 = blockIdx.x * 128;

    const int ar = tid >> 1, ac = (tid & 1) * 4;
    const int br = tid >> 5, bc = (tid & 31) * 4;

    float acc[8][8];
#pragma unroll
    for (int i = 0; i < 8; ++i)
#pragma unroll
        for (int j = 0; j < 8; ++j) acc[i][j] = 0.f;

    const float* A = g_hall;  // rows r = t*B + b, contiguous [32768,1024]
    for (int k0 = 0; k0 < Hc; k0 += 8) {
        float4 av = *(const float4*)&A[(size_t)(m0 + ar) * Hc + k0 + ac];
        float4 bv = *(const float4*)&Bm[(size_t)(k0 + br) * Oc + n0 + bc];
        __syncthreads();
        As[ac + 0][ar] = av.x; As[ac + 1][ar] = av.y;
        As[ac + 2][ar] = av.z; As[ac + 3][ar] = av.w;
        *(float4*)&Bs[br][bc] = bv;
        __syncthreads();
#pragma unroll
        for (int k = 0; k < 8; ++k) {
            float4 a0 = *(const float4*)&As[k][ty * 8];
            float4 a1 = *(const float4*)&As[k][ty * 8 + 4];
            float4 b0 = *(const float4*)&Bs[k][tx * 8];
            float4 b1 = *(const float4*)&Bs[k][tx * 8 + 4];
            float ra[8] = {a0.x, a0.y, a0.z, a0.w, a1.x, a1.y, a1.z, a1.w};
            float rb[8] = {b0.x, b0.y, b0.z, b0.w, b1.x, b1.y, b1.z, b1.w};
#pragma unroll
            for (int i = 0; i < 8; ++i)
#pragma unroll
                for (int j = 0; j < 8; ++j)
                    acc[i][j] = fmaf(ra[i], rb[j], acc[i][j]);
        }
    }
#pragma unroll
    for (int i = 0; i < 8; ++i) {
        int r = m0 + ty * 8 + i;       // r = t*B + b
        int t = r >> 6;                // /64
        int b = r & 63;
        float* orow = out + ((size_t)b * Tc + t) * Oc + n0 + tx * 8;
#pragma unroll
        for (int j = 0; j < 8; ++j)
            orow[j] = acc[i][j] + bias[n0 + tx * 8 + j];
    }
}

// ---------------------------------------------------------------------------
// Persistent recurrence kernel, K-split two-phase.
// CTA (jt, kc): jt = col tile (128 cols), kc = K chunk (64 k).
// Phase A: partial[64][128] = h_{t-1}[:, kc*64:+64] @ Whh[kc*64:+64, jt*128:+128]
//          via 8x4 register tile, float4 smem operands (3 LDS.128 : 32 FFMA per k).
// Phase B: 16384 threads sum 16 partials + xw, tanh, store h_t.
// Grid barrier between phases (monotone counter, reset by k_init).
// ---------------------------------------------------------------------------
__global__ void __launch_bounds__(256, 1) k_rnn(const float* __restrict__ Whh) {
    extern __shared__ float sm[];
    float* w_sh = sm;                    // [64][128]  32KB
    float* h_sh = sm + KCH * CT;         // [64][HSTRIDE] transposed h: [k][r]

    const int tid = threadIdx.x;
    const int cta = blockIdx.x;
    const int jt = cta & (NT - 1);       // 0..7
    const int kc = cta >> 3;             // 0..15

    // Preload this CTA's W_hh slice: w_sh[k][j] = Whh[kc*64+k][jt*128+j]
    for (int e = tid; e < KCH * CT / 4; e += 256) {
        int k = e >> 5;                  // /32 float4 per row
        int j = (e & 31) * 4;
        *(float4*)&w_sh[k * CT + j] =
            *(const float4*)&Whh[(size_t)(kc * KCH + k) * Hc + jt * CT + j];
    }

    // Phase A thread tile: 8 rows x 4 cols
    const int r0 = (tid & 7) * 8;        // batch rows r0..r0+7
    const int j0 = (tid >> 3) * 4;       // cols j0..j0+3 (within tile)

    // Phase B mapping: 16384 active threads, each 1 row x 4 cols of h
    const int gid = cta * 256 + tid;
    const bool bact = gid < (Bc * Hc / 4);
    const int brow = gid >> 8;           // 0..63
    const int bcol = (gid & 255) * 4;    // 0..1020

    unsigned target = 0;

    for (int t = 0; t < Tc; ++t) {
        // ================= Phase A =================
        if (t > 0) {
            const float* hprev = g_hall + (size_t)(t - 1) * (Bc * Hc);
            // load h chunk transposed: h_sh[k][r]
#pragma unroll
            for (int i = 0; i < 4; ++i) {
                int g = tid + i * 256;          // 0..1023 float4 groups
                int r = g >> 4;                 // row
                int kq = (g & 15) * 4;          // k within chunk
                float4 v = *(const float4*)&hprev[(size_t)r * Hc + kc * KCH + kq];
                h_sh[(kq + 0) * HSTRIDE + r] = v.x;
                h_sh[(kq + 1) * HSTRIDE + r] = v.y;
                h_sh[(kq + 2) * HSTRIDE + r] = v.z;
                h_sh[(kq + 3) * HSTRIDE + r] = v.w;
            }
            __syncthreads();

            float acc[8][4];
#pragma unroll
            for (int i = 0; i < 8; ++i)
#pragma unroll
                for (int j = 0; j < 4; ++j) acc[i][j] = 0.f;

#pragma unroll 8
            for (int k = 0; k < KCH; ++k) {
                float4 w  = *(const float4*)&w_sh[k * CT + j0];
                float4 ha = *(const float4*)&h_sh[k * HSTRIDE + r0];
                float4 hb = *(const float4*)&h_sh[k * HSTRIDE + r0 + 4];
                float hv[8] = {ha.x, ha.y, ha.z, ha.w, hb.x, hb.y, hb.z, hb.w};
                float wv[4] = {w.x, w.y, w.z, w.w};
#pragma unroll
                for (int i = 0; i < 8; ++i)
#pragma unroll
                    for (int j = 0; j < 4; ++j)
                        acc[i][j] = fmaf(hv[i], wv[j], acc[i][j]);
            }
            // write partials: g_part[kc][r][jt*128 + j]  (row stride Hc)
            float* pbase = g_part + (size_t)kc * (Bc * Hc) + jt * CT + j0;
#pragma unroll
            for (int i = 0; i < 8; ++i) {
                float4 v = make_float4(acc[i][0], acc[i][1], acc[i][2], acc[i][3]);
                *(float4*)&pbase[(size_t)(r0 + i) * Hc] = v;
            }
        }

        // ---- grid barrier 1 ----
        target += NCTA;
        __syncthreads();
        if (tid == 0) {
            __threadfence();
            atomicAdd(&g_bar, 1u);
            while (*((volatile unsigned*)&g_bar) < target) { }
            __threadfence();
        }
        __syncthreads();

        // ================= Phase B =================
        if (bact) {
            const float* xwt = g_xw + (size_t)t * (Bc * Hc) + (size_t)brow * Hc + bcol;
            float4 s = *(const float4*)xwt;
            if (t > 0) {
                const float* pb = g_part + (size_t)brow * Hc + bcol;
#pragma unroll
                for (int k2 = 0; k2 < KC; ++k2) {
                    // __ldcg: partial addresses repeat every step; bypass L1
                    float4 p = __ldcg((const float4*)(pb + (size_t)k2 * (Bc * Hc)));
                    s.x += p.x; s.y += p.y; s.z += p.z; s.w += p.w;
                }
            }
            float4 h;
            h.x = tanhf(s.x); h.y = tanhf(s.y);
            h.z = tanhf(s.z); h.w = tanhf(s.w);
            *(float4*)&g_hall[(size_t)t * (Bc * Hc) + (size_t)brow * Hc + bcol] = h;
        }

        // ---- grid barrier 2 ----
        target += NCTA;
        __syncthreads();
        if (tid == 0) {
            __threadfence();
            atomicAdd(&g_bar, 1u);
            while (*((volatile unsigned*)&g_bar) < target) { }
            __threadfence();
        }
        __syncthreads();
    }
}

// ---------------------------------------------------------------------------
extern "C" void kernel_launch(void* const* d_in, const int* in_sizes, int n_in,
                              void* d_out, int out_size) {
    const float* x    = (const float*)d_in[0];  // [64,512,512]
    const float* W_xh = (const float*)d_in[1];  // [512,1024]
    const float* W_hh = (const float*)d_in[2];  // [1024,1024]
    const float* b_h  = (const float*)d_in[3];  // [1024]
    const float* W_hy = (const float*)d_in[4];  // [1024,512]
    const float* b_y  = (const float*)d_in[5];  // [512]
    float* out = (float*)d_out;                 // [64,512,512]

    const int rnn_smem = (KCH * CT + KCH * HSTRIDE) * (int)sizeof(float); // ~50.4KB

    static bool attr_set = false;
    if (!attr_set) {
        cudaFuncSetAttribute(k_rnn, cudaFuncAttributeMaxDynamicSharedMemorySize,
                             rnn_smem);
        attr_set = true;
    }

    k_init<<<1, 32>>>();

    // xW projection: M=32768, N=1024
    dim3 gx(Hc / 128, (Bc * Tc) / 128);
    k_gemm_xw<<<gx, 256>>>(x, W_xh, b_h);

    // recurrence: persistent, 128 CTAs, two-phase K-split
    k_rnn<<<NCTA, 256, rnn_smem>>>(W_hh);

    // output projection: M=32768, N=512
    dim3 gy(Oc / 128, (Bc * Tc) / 128);
    k_gemm_y<<<gy, 256>>>(W_hy, b_y, out);
}